// round 16
// baseline (speedup 1.0000x reference)
#include <cuda_runtime.h>
#include <cuda_fp16.h>
#include <cstdint>

// GGIN: 3-layer GIN + graph readout. N=100000, E=1600000, D=128, G=1024, L=3, C=128.
// R15: precision-safe restructure at R14 speed.
//  - hg[gid] folded into gather (exact fp32) -> hg@W error is per-node-random (pools down)
//  - pg reduces to ctxc_l = ctx@Wc_l + b_l, precomputed once for all layers with
//    3-pass hi/lo tf32 correction (~exact); k_pgmma deleted from layer loop
//  - fc1/fc2 also 3-pass corrected
//  - hg_out zeroing folded into gather

#define D 128
#define MAXN 100000
#define MAXG 1024
#define MAXE 1600000
#define MAXL 4

__device__ uint2 g_xh[(size_t)MAXN * 32];
__device__ uint2 g_h0h[(size_t)MAXN * 32];
__device__ uint2 g_h1h[(size_t)MAXN * 32];
__device__ float g_m[(size_t)MAXN * D];      // fp32 m (fp16 overflows: |m|~1e5)
__device__ float g_hgA[MAXG * D];
__device__ float g_hgB[MAXG * D];
__device__ float g_ctx[MAXG * D];
__device__ float g_pgc[(size_t)MAXL * MAXG * D];   // ctx@Wc_l + b_l, all layers
__device__ float g_t[MAXG * D];
__device__ float g_lead[D];
__device__ int   g_rowptr[MAXN + 1];
__device__ int   g_cursor[MAXN];
__device__ int   g_csr[MAXE];
__device__ int   g_bsum[256];

__device__ __forceinline__ void red4(float* p, float4 v) {
    asm volatile("red.global.add.v4.f32 [%0], {%1,%2,%3,%4};"
                 :: "l"(p), "f"(v.x), "f"(v.y), "f"(v.z), "f"(v.w) : "memory");
}
__device__ __forceinline__ void red2(float* p, float x, float y) {
    asm volatile("red.global.add.v2.f32 [%0], {%1,%2};"
                 :: "l"(p), "f"(x), "f"(y) : "memory");
}
__device__ __forceinline__ float tf32r(float x) {
    float r;
    asm("cvt.rna.tf32.f32 %0, %1;" : "=f"(r) : "f"(x));
    return r;
}
__device__ __forceinline__ uint2 f42h(float4 v) {
    __half2 a = __floats2half2_rn(v.x, v.y);
    __half2 b = __floats2half2_rn(v.z, v.w);
    uint2 u;
    u.x = *(uint32_t*)&a;
    u.y = *(uint32_t*)&b;
    return u;
}
__device__ __forceinline__ void acc8(float* acc, uint4 u) {
    float2 f0 = __half22float2(*(__half2*)&u.x);
    float2 f1 = __half22float2(*(__half2*)&u.y);
    float2 f2 = __half22float2(*(__half2*)&u.z);
    float2 f3 = __half22float2(*(__half2*)&u.w);
    acc[0] += f0.x; acc[1] += f0.y; acc[2] += f1.x; acc[3] += f1.y;
    acc[4] += f2.x; acc[5] += f2.y; acc[6] += f3.x; acc[7] += f3.y;
}
__device__ __forceinline__ void mma_tf32(float* c, const uint32_t* a, uint32_t b0, uint32_t b1) {
    asm volatile(
        "mma.sync.aligned.m16n8k8.row.col.f32.tf32.tf32.f32 "
        "{%0,%1,%2,%3}, {%4,%5,%6,%7}, {%8,%9}, {%0,%1,%2,%3};"
        : "+f"(c[0]), "+f"(c[1]), "+f"(c[2]), "+f"(c[3])
        : "r"(a[0]), "r"(a[1]), "r"(a[2]), "r"(a[3]), "r"(b0), "r"(b1));
}

#define ASTRIDE 132
#define BSTRIDE 136
#define SMEM_GEMM ((128 * ASTRIDE + 128 * BSTRIDE) * 4)

// load 128x128 fp32 tile into smem, tf32-rounded; lo=1 loads the residual part
__device__ __forceinline__ void load_tile(const float4* __restrict__ src,
                                          float* __restrict__ dst, int stride,
                                          int tid, int lo) {
    #pragma unroll
    for (int i = 0; i < 16; i++) {
        int li = tid + i * 256;
        int r = li >> 5, c4 = li & 31;
        float4 v = __ldg(src + r * 32 + c4);
        float4 h;
        h.x = tf32r(v.x); h.y = tf32r(v.y); h.z = tf32r(v.z); h.w = tf32r(v.w);
        if (lo) {
            h.x = tf32r(v.x - h.x); h.y = tf32r(v.y - h.y);
            h.z = tf32r(v.z - h.z); h.w = tf32r(v.w - h.w);
        }
        *(float4*)(dst + r * stride + c4 * 4) = h;
    }
}
__device__ __forceinline__ void mma_mainloop(const uint32_t* __restrict__ Au,
                                             const uint32_t* __restrict__ Bu,
                                             float acc[2][8][4], int warpM, int warpN,
                                             int lr, int lc) {
    #pragma unroll
    for (int ks = 0; ks < 16; ks++) {
        const int kb = ks * 8;
        uint32_t a[2][4];
        #pragma unroll
        for (int mt = 0; mt < 2; mt++) {
            int r0 = warpM + mt * 16 + lr;
            a[mt][0] = Au[r0 * ASTRIDE + kb + lc];
            a[mt][1] = Au[(r0 + 8) * ASTRIDE + kb + lc];
            a[mt][2] = Au[r0 * ASTRIDE + kb + lc + 4];
            a[mt][3] = Au[(r0 + 8) * ASTRIDE + kb + lc + 4];
        }
        #pragma unroll
        for (int j = 0; j < 8; j++) {
            int nc = warpN + j * 8 + lr;
            uint32_t b0 = Bu[(kb + lc) * BSTRIDE + nc];
            uint32_t b1 = Bu[(kb + lc + 4) * BSTRIDE + nc];
            mma_tf32(acc[0][j], a[0], b0, b1);
            mma_tf32(acc[1][j], a[1], b0, b1);
        }
    }
}

__global__ void k_zeroi(int* __restrict__ p, int n) {
    int i = blockIdx.x * blockDim.x + threadIdx.x;
    if (i < n) p[i] = 0;
}

// ================= CSR build =================
__global__ void k_hist(const int* __restrict__ dst, int* __restrict__ deg, int nE) {
    int e = blockIdx.x * blockDim.x + threadIdx.x;
    if (e < nE) atomicAdd(deg + __ldg(dst + e), 1);
}
__global__ void k_bsum(const int* __restrict__ deg, int* __restrict__ bsum, int n) {
    __shared__ int sh[8];
    int base = blockIdx.x * 1024 + threadIdx.x * 4;
    int s = 0;
    #pragma unroll
    for (int j = 0; j < 4; j++) { int i = base + j; if (i < n) s += deg[i]; }
    #pragma unroll
    for (int o = 16; o > 0; o >>= 1) s += __shfl_down_sync(0xffffffffu, s, o);
    if ((threadIdx.x & 31) == 0) sh[threadIdx.x >> 5] = s;
    __syncthreads();
    if (threadIdx.x == 0) {
        int t = 0;
        for (int w = 0; w < 8; w++) t += sh[w];
        bsum[blockIdx.x] = t;
    }
}
__global__ void k_scanblk(int* __restrict__ bsum, int nb, int* __restrict__ rowptr, int n, int nE) {
    __shared__ int ws[8];
    __shared__ int wexc[8];
    int tid = threadIdx.x;
    int lane = tid & 31, warp = tid >> 5;
    int v = (tid < nb) ? bsum[tid] : 0;
    int p = v;
    #pragma unroll
    for (int o = 1; o < 32; o <<= 1) {
        int t = __shfl_up_sync(0xffffffffu, p, o);
        if (lane >= o) p += t;
    }
    if (lane == 31) ws[warp] = p;
    __syncthreads();
    if (tid == 0) {
        int acc = 0;
        #pragma unroll
        for (int w = 0; w < 8; w++) { wexc[w] = acc; acc += ws[w]; }
        rowptr[n] = nE;
    }
    __syncthreads();
    if (tid < nb) bsum[tid] = p - v + wexc[warp];
}
__global__ void k_scanfin(int* __restrict__ deg, const int* __restrict__ bsum,
                          int* __restrict__ rowptr, int* __restrict__ cursor, int n) {
    __shared__ int wsum[8];
    __shared__ int wexc[8];
    int lane = threadIdx.x & 31, warp = threadIdx.x >> 5;
    int base = blockIdx.x * 1024 + threadIdx.x * 4;
    int v[4]; int s = 0;
    #pragma unroll
    for (int j = 0; j < 4; j++) { int i = base + j; v[j] = (i < n) ? deg[i] : 0; s += v[j]; }
    int pre = s;
    #pragma unroll
    for (int o = 1; o < 32; o <<= 1) {
        int t = __shfl_up_sync(0xffffffffu, pre, o);
        if (lane >= o) pre += t;
    }
    int excl = pre - s;
    if (lane == 31) wsum[warp] = pre;
    __syncthreads();
    if (threadIdx.x == 0) {
        int acc = 0;
        #pragma unroll
        for (int w = 0; w < 8; w++) { wexc[w] = acc; acc += wsum[w]; }
    }
    __syncthreads();
    int off = bsum[blockIdx.x] + wexc[warp] + excl;
    #pragma unroll
    for (int j = 0; j < 4; j++) {
        int i = base + j;
        if (i < n) { rowptr[i] = off; cursor[i] = off; off += v[j]; }
    }
}
__global__ void k_fill(const int* __restrict__ src, const int* __restrict__ dst,
                       int* __restrict__ cursor, int* __restrict__ csr, int nE) {
    int e = blockIdx.x * blockDim.x + threadIdx.x;
    if (e < nE) {
        int pos = atomicAdd(cursor + __ldg(dst + e), 1);
        csr[pos] = __ldg(src + e);
    }
}

// ================= context =================
__global__ void k_lead(const float* __restrict__ lf, float* __restrict__ lead, int nl) {
    int d = threadIdx.x;
    float a0 = 0.f, a1 = 0.f, a2 = 0.f, a3 = 0.f;
    int r = 0;
    for (; r + 3 < nl; r += 4) {
        a0 += lf[(r + 0) * D + d];
        a1 += lf[(r + 1) * D + d];
        a2 += lf[(r + 2) * D + d];
        a3 += lf[(r + 3) * D + d];
    }
    for (; r < nl; r++) a0 += lf[r * D + d];
    lead[d] = (a0 + a1) + (a2 + a3);
}
__global__ void k_initctx(float* __restrict__ ctx, float* __restrict__ hg,
                          const float* __restrict__ lead, int n) {
    int i = blockIdx.x * blockDim.x + threadIdx.x;
    if (i < n) { ctx[i] = lead[i & (D - 1)]; hg[i] = 0.f; }
}
__global__ void k_scatter_x(const float4* __restrict__ rows, const int* __restrict__ ids,
                            float* __restrict__ out, uint2* __restrict__ xh, int n) {
    int t = blockIdx.x * blockDim.x + threadIdx.x;
    int r = t >> 5, lane = t & 31;
    if (r >= n) return;
    int g = __ldg(ids + r);
    float4 v = __ldg(rows + (size_t)r * 32 + lane);
    xh[(size_t)r * 32 + lane] = f42h(v);
    red4(out + (size_t)g * D + lane * 4, v);
}
__global__ void k_scatter_rows(const float4* __restrict__ rows, const int* __restrict__ ids,
                               float* __restrict__ out, int n) {
    int t = blockIdx.x * blockDim.x + threadIdx.x;
    int r = t >> 5, lane = t & 31;
    if (r >= n) return;
    int g = __ldg(ids + r);
    float4 v = __ldg(rows + (size_t)r * 32 + lane);
    red4(out + (size_t)g * D + lane * 4, v);
}

// ====== ctxc: pgc_l = ctx @ Wc_l + b_l for all layers; 3-pass tf32 correction ======
// grid = (G/128, L)
__global__ void __launch_bounds__(256, 1)
k_ctxc(const float4* __restrict__ ctx4, const float4* __restrict__ WcAll,
       const float* __restrict__ bAll, float* __restrict__ pgc, int G) {
    extern __shared__ float smem[];
    float* As = smem;
    float* Bs = smem + 128 * ASTRIDE;
    const int tid = threadIdx.x;
    const int wid = tid >> 5, lane = tid & 31;
    const int g0 = blockIdx.x * 128;
    const int l = blockIdx.y;
    const float4* B4 = WcAll + (size_t)l * D * D / 4;
    const float* bias = bAll + l * D;
    float* out = pgc + (size_t)l * G * D;
    const int warpM = (wid & 3) * 32;
    const int warpN = (wid >> 2) * 64;
    const int lr = lane >> 2, lc = lane & 3;

    float acc[2][8][4];
    #pragma unroll
    for (int mt = 0; mt < 2; mt++)
        #pragma unroll
        for (int j = 0; j < 8; j++)
            #pragma unroll
            for (int q = 0; q < 4; q++) acc[mt][j][q] = 0.f;

    // pass 1: Ah * Bh
    load_tile(ctx4 + (size_t)g0 * 32, As, ASTRIDE, tid, 0);
    load_tile(B4, Bs, BSTRIDE, tid, 0);
    __syncthreads();
    mma_mainloop((const uint32_t*)As, (const uint32_t*)Bs, acc, warpM, warpN, lr, lc);
    __syncthreads();
    // pass 2: Al * Bh
    load_tile(ctx4 + (size_t)g0 * 32, As, ASTRIDE, tid, 1);
    __syncthreads();
    mma_mainloop((const uint32_t*)As, (const uint32_t*)Bs, acc, warpM, warpN, lr, lc);
    __syncthreads();
    // pass 3: Ah * Bl
    load_tile(ctx4 + (size_t)g0 * 32, As, ASTRIDE, tid, 0);
    load_tile(B4, Bs, BSTRIDE, tid, 1);
    __syncthreads();
    mma_mainloop((const uint32_t*)As, (const uint32_t*)Bs, acc, warpM, warpN, lr, lc);

    #pragma unroll
    for (int mt = 0; mt < 2; mt++) {
        #pragma unroll
        for (int half = 0; half < 2; half++) {
            int mg = g0 + warpM + mt * 16 + half * 8 + lr;
            #pragma unroll
            for (int j = 0; j < 8; j++) {
                int nc = warpN + j * 8 + lc * 2;
                float2 bv = __ldg((const float2*)(bias + nc));
                *(float2*)(out + (size_t)mg * D + nc) =
                    make_float2(acc[mt][j][half * 2 + 0] + bv.x,
                                acc[mt][j][half * 2 + 1] + bv.y);
            }
        }
    }
}

// ====== fc via mma, 3-pass corrected: out = (relu?)(in@W + bias). grid = G/128 ======
__global__ void __launch_bounds__(256, 1)
k_fcmma(const float4* __restrict__ in4, const float4* __restrict__ W4,
        const float* __restrict__ bias, float* __restrict__ out, int do_relu) {
    extern __shared__ float smem[];
    float* As = smem;
    float* Bs = smem + 128 * ASTRIDE;
    const int tid = threadIdx.x;
    const int wid = tid >> 5, lane = tid & 31;
    const int g0 = blockIdx.x * 128;
    const int warpM = (wid & 3) * 32;
    const int warpN = (wid >> 2) * 64;
    const int lr = lane >> 2, lc = lane & 3;

    float acc[2][8][4];
    #pragma unroll
    for (int mt = 0; mt < 2; mt++)
        #pragma unroll
        for (int j = 0; j < 8; j++)
            #pragma unroll
            for (int q = 0; q < 4; q++) acc[mt][j][q] = 0.f;

    load_tile(in4 + (size_t)g0 * 32, As, ASTRIDE, tid, 0);
    load_tile(W4, Bs, BSTRIDE, tid, 0);
    __syncthreads();
    mma_mainloop((const uint32_t*)As, (const uint32_t*)Bs, acc, warpM, warpN, lr, lc);
    __syncthreads();
    load_tile(in4 + (size_t)g0 * 32, As, ASTRIDE, tid, 1);
    __syncthreads();
    mma_mainloop((const uint32_t*)As, (const uint32_t*)Bs, acc, warpM, warpN, lr, lc);
    __syncthreads();
    load_tile(in4 + (size_t)g0 * 32, As, ASTRIDE, tid, 0);
    load_tile(W4, Bs, BSTRIDE, tid, 1);
    __syncthreads();
    mma_mainloop((const uint32_t*)As, (const uint32_t*)Bs, acc, warpM, warpN, lr, lc);

    #pragma unroll
    for (int mt = 0; mt < 2; mt++) {
        #pragma unroll
        for (int half = 0; half < 2; half++) {
            int mg = g0 + warpM + mt * 16 + half * 8 + lr;
            #pragma unroll
            for (int j = 0; j < 8; j++) {
                int nc = warpN + j * 8 + lc * 2;
                float2 bv = __ldg((const float2*)(bias + nc));
                float o0 = acc[mt][j][half * 2 + 0] + bv.x;
                float o1 = acc[mt][j][half * 2 + 1] + bv.y;
                if (do_relu) { o0 = fmaxf(o0, 0.f); o1 = fmaxf(o1, 0.f); }
                *(float2*)(out + (size_t)mg * D + nc) = make_float2(o0, o1);
            }
        }
    }
}

// ====== gather: m[v] = (1+eps)h[v] + sum_nbrs h[u] + hg[gid[v]]; zero hgOut ======
__global__ void k_gather_h2(const uint4* __restrict__ h4, const int* __restrict__ rowptr,
                            const int* __restrict__ csr, const int* __restrict__ gid,
                            const float* __restrict__ hgIn, float4* __restrict__ hgOut4,
                            float4* __restrict__ m4, const float* __restrict__ epsArr,
                            int l, int n, int nHg4) {
    int t = blockIdx.x * blockDim.x + threadIdx.x;
    if (t < nHg4) hgOut4[t] = make_float4(0.f, 0.f, 0.f, 0.f);
    int v = t >> 4;
    int sl = t & 15;
    if (v >= n) return;
    const float sc = 1.0f + __ldg(epsArr + l);
    int beg = __ldg(rowptr + v), end = __ldg(rowptr + v + 1);

    float acc[8];
    {
        uint4 hv = __ldg(h4 + (size_t)v * 16 + sl);
        float2 f0 = __half22float2(*(__half2*)&hv.x);
        float2 f1 = __half22float2(*(__half2*)&hv.y);
        float2 f2 = __half22float2(*(__half2*)&hv.z);
        float2 f3 = __half22float2(*(__half2*)&hv.w);
        acc[0] = sc * f0.x; acc[1] = sc * f0.y; acc[2] = sc * f1.x; acc[3] = sc * f1.y;
        acc[4] = sc * f2.x; acc[5] = sc * f2.y; acc[6] = sc * f3.x; acc[7] = sc * f3.y;
    }
    // exact fp32 hg row (graph-level term folded into m)
    {
        int gv = __ldg(gid + v);
        const float4* hgr = (const float4*)(hgIn + (size_t)gv * D) + sl * 2;
        float4 e0 = __ldg(hgr), e1 = __ldg(hgr + 1);
        acc[0] += e0.x; acc[1] += e0.y; acc[2] += e0.z; acc[3] += e0.w;
        acc[4] += e1.x; acc[5] += e1.y; acc[6] += e1.z; acc[7] += e1.w;
    }
    int i = beg;
    for (; i + 3 < end; i += 4) {
        int u0 = __ldg(csr + i), u1 = __ldg(csr + i + 1);
        int u2 = __ldg(csr + i + 2), u3 = __ldg(csr + i + 3);
        uint4 a = __ldg(h4 + (size_t)u0 * 16 + sl);
        uint4 b = __ldg(h4 + (size_t)u1 * 16 + sl);
        uint4 c = __ldg(h4 + (size_t)u2 * 16 + sl);
        uint4 d = __ldg(h4 + (size_t)u3 * 16 + sl);
        acc8(acc, a); acc8(acc, b); acc8(acc, c); acc8(acc, d);
    }
    for (; i < end; i++) {
        int u0 = __ldg(csr + i);
        uint4 a = __ldg(h4 + (size_t)u0 * 16 + sl);
        acc8(acc, a);
    }
    m4[(size_t)v * 32 + sl * 2]     = make_float4(acc[0], acc[1], acc[2], acc[3]);
    m4[(size_t)v * 32 + sl * 2 + 1] = make_float4(acc[4], acc[5], acc[6], acc[7]);
}

// ================= node GEMM: mma.sync tf32 =================
__global__ void __launch_bounds__(256, 1)
k_gemm(const float4* __restrict__ M4, const float4* __restrict__ Wl4,
       const float* __restrict__ pgv, const int* __restrict__ gid,
       uint32_t* __restrict__ HoutH, float* __restrict__ hgOut, int nRows, int storeH) {
    extern __shared__ float smem[];
    float* As = smem;
    float* Bs = smem + 128 * ASTRIDE;
    const int tid = threadIdx.x;
    const int wid = tid >> 5, lane = tid & 31;
    const int m0 = blockIdx.x * 128;
    const int warpM = (wid & 3) * 32;
    const int warpN = (wid >> 2) * 64;
    const int lr = lane >> 2, lc = lane & 3;

    #pragma unroll
    for (int i = 0; i < 16; i++) {
        int li = tid + i * 256;
        int row = li >> 5, k4 = li & 31;
        int mg = m0 + row;
        float4 v = (mg < nRows) ? __ldg(M4 + (size_t)mg * 32 + k4)
                                : make_float4(0.f, 0.f, 0.f, 0.f);
        v.x = tf32r(v.x); v.y = tf32r(v.y); v.z = tf32r(v.z); v.w = tf32r(v.w);
        *(float4*)(As + row * ASTRIDE + k4 * 4) = v;
    }
    load_tile(Wl4, Bs, BSTRIDE, tid, 0);
    __syncthreads();

    float acc[2][8][4];
    #pragma unroll
    for (int mt = 0; mt < 2; mt++)
        #pragma unroll
        for (int j = 0; j < 8; j++)
            #pragma unroll
            for (int q = 0; q < 4; q++) acc[mt][j][q] = 0.f;

    mma_mainloop((const uint32_t*)As, (const uint32_t*)Bs, acc, warpM, warpN, lr, lc);

    #pragma unroll
    for (int mt = 0; mt < 2; mt++) {
        #pragma unroll
        for (int half = 0; half < 2; half++) {
            int mg = m0 + warpM + mt * 16 + half * 8 + lr;
            if (mg >= nRows) continue;
            int g = __ldg(gid + mg);
            const float* pgr = pgv + (size_t)g * D;
            #pragma unroll
            for (int j = 0; j < 8; j++) {
                int nc = warpN + j * 8 + lc * 2;
                float c0 = acc[mt][j][half * 2 + 0];
                float c1 = acc[mt][j][half * 2 + 1];
                float2 p = __ldg((const float2*)(pgr + nc));
                float o0 = fmaxf(c0 + p.x, 0.f);
                float o1 = fmaxf(c1 + p.y, 0.f);
                if (storeH) {
                    __half2 hv = __floats2half2_rn(o0, o1);
                    HoutH[((size_t)mg * D + nc) >> 1] = *(uint32_t*)&hv;
                }
                red2(hgOut + (size_t)g * D + nc, o0, o1);
            }
        }
    }
}

extern "C" void kernel_launch(void* const* d_in, const int* in_sizes, int n_in,
                              void* d_out, int out_size) {
    const float* x        = (const float*)d_in[0];
    const int*   src      = (const int*)d_in[1];
    const int*   dst      = (const int*)d_in[2];
    const int*   gids     = (const int*)d_in[3];
    const float* initf    = (const float*)d_in[4];
    const int*   init_ids = (const int*)d_in[5];
    const float* leadf    = (const float*)d_in[6];
    const float* W        = (const float*)d_in[7];
    const float* Wc       = (const float*)d_in[8];
    const float* b        = (const float*)d_in[9];
    const float* eps      = (const float*)d_in[10];
    const float* fc1_w    = (const float*)d_in[11];
    const float* fc1_b    = (const float*)d_in[12];
    const float* fc2_w    = (const float*)d_in[13];
    const float* fc2_b    = (const float*)d_in[14];

    const int N  = in_sizes[0] / D;
    const int E  = in_sizes[1];
    const int NI = in_sizes[4] / D;
    const int NL = in_sizes[6] / D;
    const int L  = in_sizes[10];
    const int G  = out_size / D;

    uint2 *xh, *h0h, *h1h;
    float *mbuf, *hgA, *hgB, *ctx, *pgc, *tbuf, *lead;
    int *rowptr, *cursor, *csr, *bsum;
    cudaGetSymbolAddress((void**)&xh, g_xh);
    cudaGetSymbolAddress((void**)&h0h, g_h0h);
    cudaGetSymbolAddress((void**)&h1h, g_h1h);
    cudaGetSymbolAddress((void**)&mbuf, g_m);
    cudaGetSymbolAddress((void**)&hgA, g_hgA);
    cudaGetSymbolAddress((void**)&hgB, g_hgB);
    cudaGetSymbolAddress((void**)&ctx, g_ctx);
    cudaGetSymbolAddress((void**)&pgc, g_pgc);
    cudaGetSymbolAddress((void**)&tbuf, g_t);
    cudaGetSymbolAddress((void**)&lead, g_lead);
    cudaGetSymbolAddress((void**)&rowptr, g_rowptr);
    cudaGetSymbolAddress((void**)&cursor, g_cursor);
    cudaGetSymbolAddress((void**)&csr, g_csr);
    cudaGetSymbolAddress((void**)&bsum, g_bsum);

    cudaFuncSetAttribute(k_gemm, cudaFuncAttributeMaxDynamicSharedMemorySize, SMEM_GEMM);
    cudaFuncSetAttribute(k_ctxc, cudaFuncAttributeMaxDynamicSharedMemorySize, SMEM_GEMM);
    cudaFuncSetAttribute(k_fcmma, cudaFuncAttributeMaxDynamicSharedMemorySize, SMEM_GEMM);

    const int NB = (N + 1023) / 1024;
    const int GB = G / 128;   // 8

    // CSR build
    k_zeroi<<<(N + 255) / 256, 256>>>(cursor, N);
    k_hist<<<(E + 255) / 256, 256>>>(dst, cursor, E);
    k_bsum<<<NB, 256>>>(cursor, bsum, N);
    k_scanblk<<<1, 256>>>(bsum, NB, rowptr, N, E);
    k_scanfin<<<NB, 256>>>(cursor, bsum, rowptr, cursor, N);
    k_fill<<<(E + 255) / 256, 256>>>(src, dst, cursor, csr, E);

    // context (+ fused x->fp16), then all-layer ctxc with 3-pass correction
    k_lead<<<1, D>>>(leadf, lead, NL);
    k_initctx<<<(G * D + 255) / 256, 256>>>(ctx, hgA, lead, G * D);
    k_scatter_x<<<(N * 32 + 255) / 256, 256>>>((const float4*)x, gids, hgA, xh, N);
    k_scatter_rows<<<(NI * 32 + 255) / 256, 256>>>((const float4*)initf, init_ids, ctx, NI);
    {
        dim3 grid(GB, L);
        k_ctxc<<<grid, 256, SMEM_GEMM>>>((const float4*)ctx, (const float4*)Wc, b, pgc, G);
    }

    const uint2* hin = xh;
    uint2* hbuf[2] = {h0h, h1h};
    float* hg_in = hgA;
    float* hg_out = hgB;

    for (int l = 0; l < L; l++) {
        uint2* hout = hbuf[l & 1];
        int storeH = (l + 1 < L) ? 1 : 0;
        k_gather_h2<<<(N * 16 + 255) / 256, 256>>>(
            (const uint4*)hin, rowptr, csr, gids, hg_in, (float4*)hg_out,
            (float4*)mbuf, eps, l, N, G * D / 4);
        k_gemm<<<(N + 127) / 128, 256, SMEM_GEMM>>>(
            (const float4*)mbuf, (const float4*)(W + (size_t)l * D * D),
            pgc + (size_t)l * G * D, gids, (uint32_t*)hout, hg_out, N, storeH);
        hin = hout;
        float* tmp = hg_in; hg_in = hg_out; hg_out = tmp;
    }

    k_fcmma<<<GB, 256, SMEM_GEMM>>>((const float4*)hg_in, (const float4*)fc1_w,
                                    fc1_b, tbuf, 1);
    k_fcmma<<<GB, 256, SMEM_GEMM>>>((const float4*)tbuf, (const float4*)fc2_w,
                                    fc2_b, (float*)d_out, 0);
}